// round 13
// baseline (speedup 1.0000x reference)
#include <cuda_runtime.h>
#include <cuda_bf16.h>
#include <cuda_fp16.h>
#include <mma.h>
#include <cstdint>

using namespace nvcuda;

// Problem constants (from reference: N=100000, E=3200000, IN=256, OUT=128).
#define MAXN 100000
#define MAXE 3200000
#define INF  256
#define OUTF 128

// -------- static device scratch (no allocations allowed) --------
__device__ __half g_supportH[(size_t)MAXN * OUTF]; // 25.6 MB (fp16 support)
__device__ int   g_cnt[MAXN + 1];
__device__ int   g_rowptr[MAXN + 1];
__device__ int   g_wp[MAXN + 1];
__device__ int2  g_edge[MAXE];                     // packed (col, val-bits)
__device__ int   g_bsum[1024];
__device__ float g_Wt[INF * OUTF];                 // W pre-rounded to tf32 (RN)

// -------- side stream + events for fork-join graph capture --------
__global__ void warm_kernel() {}

struct SideStream {
    cudaStream_t s2;
    cudaEvent_t  ev_fork, ev_join;
    SideStream() {
        cudaStreamCreateWithFlags(&s2, cudaStreamNonBlocking);
        cudaEventCreateWithFlags(&ev_fork, cudaEventDisableTiming);
        cudaEventCreateWithFlags(&ev_join, cudaEventDisableTiming);
        warm_kernel<<<1, 32>>>();
        warm_kernel<<<1, 32, 0, s2>>>();
        cudaEventRecord(ev_fork, 0);
        cudaStreamWaitEvent(s2, ev_fork, 0);
        cudaEventRecord(ev_join, s2);
        cudaStreamWaitEvent(0, ev_join, 0);
        cudaDeviceSynchronize();
    }
};
static SideStream g_ss;

// ============ W prep: round to tf32 (RN) once (GEMM branch) ============
__global__ void wprep_kernel(const float* __restrict__ W, float* __restrict__ Wt)
{
    int idx = blockIdx.x * 256 + threadIdx.x;
    if (idx < INF * OUTF)
        Wt[idx] = wmma::__float_to_tf32(W[idx]);
}

// ============ zero cnt (CSR branch) ============
__global__ void zero_cnt_kernel(int* cnt, int n)
{
    int i = blockIdx.x * blockDim.x + threadIdx.x;
    if (i <= n) cnt[i] = 0;
}

// ============ GEMM via wmma tf32 (m16n16k8), cp.async double-buffered A ======
// CTA tile 128(M) x 128(N); K=256 in 4 chunks of BK=64.
// 8 warps: warpM = wid>>1 (32 M-rows, 2 frags), warpN = wid&1 (64 N-cols, 4 frags).
// A = X fp32 staged directly (converted to tf32 in-register), double buffer.
// B = Wt fp32 (pre-rounded), single buffer, cp.async per chunk.

#define BK 64
#define XA_LDF 68                        // floats per A smem row (64 + 4 pad)
#define XA_ROW_B (XA_LDF * 4)            // 272
#define XA_BUF_B (128 * XA_ROW_B)        // 34816
#define WT_LDF 132                       // floats per W smem row (128 + 4 pad)
#define WT_ROW_B (WT_LDF * 4)            // 528
#define WT_BUF_B (64 * WT_ROW_B)         // 33792
#define SM_X0 0
#define SM_X1 XA_BUF_B
#define SM_W  (2 * XA_BUF_B)             // 69632
#define SM_TOTAL (SM_W + WT_BUF_B)       // 103424

__device__ __forceinline__ void cp_async16(uint32_t saddr, const void* gptr) {
    asm volatile("cp.async.cg.shared.global [%0], [%1], 16;"
                 :: "r"(saddr), "l"(gptr));
}
__device__ __forceinline__ void cp_async_commit() {
    asm volatile("cp.async.commit_group;");
}
__device__ __forceinline__ void cp_async_wait_all() {
    asm volatile("cp.async.wait_group 0;" ::: "memory");
}
__device__ __forceinline__ void cp_async_wait_1() {
    asm volatile("cp.async.wait_group 1;" ::: "memory");
}

__device__ __forceinline__ uint32_t smem_u32(const void* p) {
    uint32_t a;
    asm("{ .reg .u64 t; cvta.to.shared.u64 t, %1; cvt.u32.u64 %0, t; }"
        : "=r"(a) : "l"(p));
    return a;
}

__global__ __launch_bounds__(256, 2) void gemm_wmma_kernel(
    const float* __restrict__ X,
    const float* __restrict__ Wt,
    __half* __restrict__ SH, int nrows)
{
    extern __shared__ char smem[];
    const int tid = threadIdx.x;
    const int wid = tid >> 5;
    const int bm = blockIdx.x * 128;
    const int warpM = wid >> 1;
    const int warpN = wid & 1;
    const uint32_t sm_base = smem_u32(smem);

    wmma::fragment<wmma::accumulator, 16, 16, 8, float> acc[2][4];
#pragma unroll
    for (int i = 0; i < 2; i++)
#pragma unroll
        for (int j = 0; j < 4; j++)
            wmma::fill_fragment(acc[i][j], 0.0f);

    // ---- prefetch A chunk 0 into X0 (group 0) ----
    {
#pragma unroll
        for (int it = 0; it < 8; it++) {
            int idx = tid + it * 256;
            int r = idx >> 4, c4 = idx & 15;       // 16 x 16B per row
            int grow = bm + r;
            uint32_t so = sm_base + SM_X0 + (uint32_t)r * XA_ROW_B + (uint32_t)c4 * 16;
            if (grow < nrows)
                cp_async16(so, X + (size_t)grow * INF + c4 * 4);
            else
                *reinterpret_cast<uint4*>(smem + SM_X0 + r * XA_ROW_B + c4 * 16) =
                    make_uint4(0u, 0u, 0u, 0u);
        }
        cp_async_commit();
    }

    for (int c = 0; c < 4; c++) {
        const int buf = c & 1;
        // ---- stage W chunk c (64 x 128 fp32) via cp.async ----
#pragma unroll
        for (int it = 0; it < 8; it++) {
            int idx = tid + it * 256;               // 2048 x 16B
            int r = idx >> 5, cc = idx & 31;        // 32 x 16B per row
            uint32_t so = sm_base + SM_W + (uint32_t)r * WT_ROW_B + (uint32_t)cc * 16;
            cp_async16(so, Wt + (size_t)(c * BK + r) * OUTF + cc * 4);
        }
        cp_async_commit();

        // ---- prefetch A chunk c+1 into the other buffer ----
        if (c < 3) {
#pragma unroll
            for (int it = 0; it < 8; it++) {
                int idx = tid + it * 256;
                int r = idx >> 4, c4 = idx & 15;
                int grow = bm + r;
                uint32_t so = sm_base + (buf ? SM_X0 : SM_X1)
                              + (uint32_t)r * XA_ROW_B + (uint32_t)c4 * 16;
                if (grow < nrows)
                    cp_async16(so, X + (size_t)grow * INF + (c + 1) * BK + c4 * 4);
            }
            cp_async_commit();
            cp_async_wait_1();     // A(c) + W(c) done; A(c+1) still in flight
        } else {
            cp_async_wait_all();
        }
        __syncthreads();

        const float* AS = reinterpret_cast<const float*>(smem + (buf ? SM_X1 : SM_X0));
        const float* WS = reinterpret_cast<const float*>(smem + SM_W);

#pragma unroll
        for (int ks = 0; ks < 8; ks++) {
            wmma::fragment<wmma::matrix_a, 16, 16, 8, wmma::precision::tf32, wmma::row_major> a[2];
#pragma unroll
            for (int i = 0; i < 2; i++) {
                int arow = warpM * 32 + i * 16;
                wmma::load_matrix_sync(a[i], AS + arow * XA_LDF + ks * 8, XA_LDF);
#pragma unroll
                for (int e = 0; e < a[i].num_elements; e++)
                    a[i].x[e] = wmma::__float_to_tf32(a[i].x[e]);
            }
#pragma unroll
            for (int j = 0; j < 4; j++) {
                wmma::fragment<wmma::matrix_b, 16, 16, 8, wmma::precision::tf32, wmma::row_major> b;
                int bcol = warpN * 64 + j * 16;
                wmma::load_matrix_sync(b, WS + (ks * 8) * WT_LDF + bcol, WT_LDF);
                // Wt pre-rounded to tf32 in wprep; bits already valid tf32
#pragma unroll
                for (int i = 0; i < 2; i++)
                    wmma::mma_sync(acc[i][j], a[i], b, acc[i][j]);
            }
        }
        __syncthreads();
    }

    // ---- epilogue: stage fp32 via smem, convert to fp16, coalesced store ----
    float* F = reinterpret_cast<float*>(smem);     // 128x128 fp32 = 64KB
#pragma unroll
    for (int i = 0; i < 2; i++)
#pragma unroll
        for (int j = 0; j < 4; j++)
            wmma::store_matrix_sync(F + (warpM * 32 + i * 16) * 128 + warpN * 64 + j * 16,
                                    acc[i][j], 128, wmma::mem_row_major);
    __syncthreads();
    const float4* F4 = reinterpret_cast<const float4*>(F);
    uint2* SH2 = reinterpret_cast<uint2*>(SH);
#pragma unroll
    for (int it = 0; it < 16; it++) {
        int idx = tid + it * 256;
        int r = idx >> 5, c4 = idx & 31;
        int grow = bm + r;
        if (grow < nrows) {
            float4 f = F4[idx];
            __half2 p0 = __floats2half2_rn(f.x, f.y);
            __half2 p1 = __floats2half2_rn(f.z, f.w);
            SH2[(size_t)grow * 32 + c4] =
                make_uint2(*reinterpret_cast<uint32_t*>(&p0),
                           *reinterpret_cast<uint32_t*>(&p1));
        }
    }
}

// ================= CSR build =================
__global__ void hist_kernel(const int* __restrict__ row, int* __restrict__ cnt, int E)
{
    int b = blockIdx.x * blockDim.x + threadIdx.x;
    int e = b * 4;
    if (e + 3 < E) {
        int4 r4 = *reinterpret_cast<const int4*>(row + e);
        atomicAdd(&cnt[r4.x], 1);
        atomicAdd(&cnt[r4.y], 1);
        atomicAdd(&cnt[r4.z], 1);
        atomicAdd(&cnt[r4.w], 1);
    } else {
        for (int k = e; k < E; k++) atomicAdd(&cnt[row[k]], 1);
    }
}

__global__ __launch_bounds__(1024) void scan1_kernel(
    const int* __restrict__ cnt, int* __restrict__ excl, int* __restrict__ bsum, int n)
{
    __shared__ int s[1024];
    int t = threadIdx.x;
    int gid = blockIdx.x * 1024 + t;
    int v = (gid < n) ? cnt[gid] : 0;
    s[t] = v;
    __syncthreads();
#pragma unroll
    for (int off = 1; off < 1024; off <<= 1) {
        int x = (t >= off) ? s[t - off] : 0;
        __syncthreads();
        s[t] += x;
        __syncthreads();
    }
    if (gid < n) excl[gid] = s[t] - v;
    if (t == 1023) bsum[blockIdx.x] = s[1023];
}

__global__ __launch_bounds__(1024) void scan2_kernel(int* bsum, int nb)
{
    __shared__ int s[1024];
    int t = threadIdx.x;
    int v = (t < nb) ? bsum[t] : 0;
    s[t] = v;
    __syncthreads();
#pragma unroll
    for (int off = 1; off < 1024; off <<= 1) {
        int x = (t >= off) ? s[t - off] : 0;
        __syncthreads();
        s[t] += x;
        __syncthreads();
    }
    if (t < nb) bsum[t] = s[t] - v;
}

__global__ void scan3_kernel(int* __restrict__ rowptr, int* __restrict__ wp,
                             const int* __restrict__ bsum, int n, int E)
{
    int i = blockIdx.x * blockDim.x + threadIdx.x;
    if (i < n) {
        int v = rowptr[i] + bsum[i >> 10];
        rowptr[i] = v;
        wp[i] = v;
    }
    if (i == 0) rowptr[n] = E;
}

__global__ void scatter_kernel(const int* __restrict__ row, const int* __restrict__ col,
                               const float* __restrict__ vals, int* __restrict__ wp,
                               int2* __restrict__ edge, int E)
{
    int b = blockIdx.x * blockDim.x + threadIdx.x;
    int e = b * 4;
    if (e + 3 < E) {
        int4   r4 = *reinterpret_cast<const int4*>(row + e);
        int4   c4 = *reinterpret_cast<const int4*>(col + e);
        float4 v4 = *reinterpret_cast<const float4*>(vals + e);
        int p;
        p = atomicAdd(&wp[r4.x], 1); edge[p] = make_int2(c4.x, __float_as_int(v4.x));
        p = atomicAdd(&wp[r4.y], 1); edge[p] = make_int2(c4.y, __float_as_int(v4.y));
        p = atomicAdd(&wp[r4.z], 1); edge[p] = make_int2(c4.z, __float_as_int(v4.z));
        p = atomicAdd(&wp[r4.w], 1); edge[p] = make_int2(c4.w, __float_as_int(v4.w));
    } else {
        for (int k = e; k < E; k++) {
            int p = atomicAdd(&wp[row[k]], 1);
            edge[p] = make_int2(col[k], __float_as_int(vals[k]));
        }
    }
}

// ======= SpMM (fp16 gather, MLP=8): out[r] = sum val*support16[col] + bias ===
// One warp per destination row; lane owns 4 consecutive output cols.
// Inner loop batches 8 independent gathers to hide L2 latency.
__global__ __launch_bounds__(256) void spmm_kernel(
    const int* __restrict__ rowptr, const int2* __restrict__ edge,
    const __half* __restrict__ SH,
    const float* __restrict__ bias, float* __restrict__ out, int nrows)
{
    int warp = (blockIdx.x * blockDim.x + threadIdx.x) >> 5;
    int lane = threadIdx.x & 31;
    if (warp >= nrows) return;

    int start = rowptr[warp];
    int end   = rowptr[warp + 1];

    const uint2* S2 = reinterpret_cast<const uint2*>(SH);
    float4 acc = make_float4(0.f, 0.f, 0.f, 0.f);

    for (int j0 = start; j0 < end; j0 += 32) {
        int jj = j0 + lane;
        int2 ev = (jj < end) ? edge[jj] : make_int2(0, 0);
        int m = min(32, end - j0);
        int t = 0;
        for (; t + 8 <= m; t += 8) {
            int   c[8];
            float v[8];
            uint2 u[8];
#pragma unroll
            for (int q = 0; q < 8; q++) {
                c[q] = __shfl_sync(0xffffffffu, ev.x, t + q);
                v[q] = __int_as_float(__shfl_sync(0xffffffffu, ev.y, t + q));
            }
#pragma unroll
            for (int q = 0; q < 8; q++)
                u[q] = S2[(size_t)c[q] * 32 + lane];
#pragma unroll
            for (int q = 0; q < 8; q++) {
                __half2 h01 = *reinterpret_cast<__half2*>(&u[q].x);
                __half2 h23 = *reinterpret_cast<__half2*>(&u[q].y);
                float2 f01 = __half22float2(h01);
                float2 f23 = __half22float2(h23);
                acc.x = fmaf(v[q], f01.x, acc.x);
                acc.y = fmaf(v[q], f01.y, acc.y);
                acc.z = fmaf(v[q], f23.x, acc.z);
                acc.w = fmaf(v[q], f23.y, acc.w);
            }
        }
        for (; t < m; t++) {
            int   ct = __shfl_sync(0xffffffffu, ev.x, t);
            float vt = __int_as_float(__shfl_sync(0xffffffffu, ev.y, t));
            uint2 u = S2[(size_t)ct * 32 + lane];
            __half2 h01 = *reinterpret_cast<__half2*>(&u.x);
            __half2 h23 = *reinterpret_cast<__half2*>(&u.y);
            float2 f01 = __half22float2(h01);
            float2 f23 = __half22float2(h23);
            acc.x = fmaf(vt, f01.x, acc.x);
            acc.y = fmaf(vt, f01.y, acc.y);
            acc.z = fmaf(vt, f23.x, acc.z);
            acc.w = fmaf(vt, f23.y, acc.w);
        }
    }

    float4 b = reinterpret_cast<const float4*>(bias)[lane];
    acc.x += b.x; acc.y += b.y; acc.z += b.z; acc.w += b.w;
    reinterpret_cast<float4*>(out)[(size_t)warp * 32 + lane] = acc;
}

// ================= launch =================
extern "C" void kernel_launch(void* const* d_in, const int* in_sizes, int n_in,
                              void* d_out, int out_size)
{
    const float* x        = (const float*)d_in[0];   // [N, IN]
    const float* adj_vals = (const float*)d_in[1];   // [E]
    const float* weight   = (const float*)d_in[2];   // [IN, OUT]
    const float* bias     = (const float*)d_in[3];   // [OUT]
    const int*   row      = (const int*)d_in[4];     // [E]
    const int*   col      = (const int*)d_in[5];     // [E]

    const int outf = in_sizes[3];                    // 128
    const int inf  = in_sizes[2] / outf;             // 256
    const int N    = in_sizes[0] / inf;              // 100000
    const int E    = in_sizes[1];                    // 3200000
    (void)inf; (void)n_in; (void)out_size;

    __half* supportH; cudaGetSymbolAddress((void**)&supportH, g_supportH);
    int*    cnt;      cudaGetSymbolAddress((void**)&cnt,     g_cnt);
    int*    rowptr;   cudaGetSymbolAddress((void**)&rowptr,  g_rowptr);
    int*    wp;       cudaGetSymbolAddress((void**)&wp,      g_wp);
    int2*   edge;     cudaGetSymbolAddress((void**)&edge,    g_edge);
    int*    bsum;     cudaGetSymbolAddress((void**)&bsum,    g_bsum);
    float*  wt;       cudaGetSymbolAddress((void**)&wt,      g_Wt);

    cudaStream_t s2 = g_ss.s2;

    // ---- fork: CSR branch on s2, GEMM branch on legacy stream ----
    cudaEventRecord(g_ss.ev_fork, 0);
    cudaStreamWaitEvent(s2, g_ss.ev_fork, 0);

    // Branch A: W tf32 round + tensor-core tf32 GEMM (fp16 output)
    wprep_kernel<<<(INF * OUTF + 255) / 256, 256>>>(weight, wt);
    cudaFuncSetAttribute(gemm_wmma_kernel,
                         cudaFuncAttributeMaxDynamicSharedMemorySize, SM_TOTAL);
    gemm_wmma_kernel<<<(N + 127) / 128, 256, SM_TOTAL>>>(x, wt, supportH, N);

    // Branch B: CSR build (packed edges)
    zero_cnt_kernel<<<(N + 256) / 256, 256, 0, s2>>>(cnt, N);
    hist_kernel<<<(E / 4 + 255) / 256, 256, 0, s2>>>(row, cnt, E);
    int nb = (N + 1023) / 1024;
    scan1_kernel<<<nb, 1024, 0, s2>>>(cnt, rowptr, bsum, N);
    scan2_kernel<<<1, 1024, 0, s2>>>(bsum, nb);
    scan3_kernel<<<(N + 255) / 256, 256, 0, s2>>>(rowptr, wp, bsum, N, E);
    scatter_kernel<<<(E / 4 + 255) / 256, 256, 0, s2>>>(row, col, adj_vals, wp, edge, E);

    // ---- join: SpMM needs both branches ----
    cudaEventRecord(g_ss.ev_join, s2);
    cudaStreamWaitEvent(0, g_ss.ev_join, 0);

    spmm_kernel<<<(N + 7) / 8, 256>>>(rowptr, edge, supportH, bias,
                                      (float*)d_out, N);
}

// round 15
// speedup vs baseline: 1.0951x; 1.0951x over previous
#include <cuda_runtime.h>
#include <cuda_bf16.h>
#include <cuda_fp16.h>
#include <mma.h>
#include <cstdint>

using namespace nvcuda;

// Problem constants (from reference: N=100000, E=3200000, IN=256, OUT=128).
#define MAXN 100000
#define MAXE 3200000
#define INF  256
#define OUTF 128

// -------- static device scratch (no allocations allowed) --------
__device__ __half g_supportH[(size_t)MAXN * OUTF]; // 25.6 MB (fp16 support)
__device__ int   g_cnt[MAXN + 1];
__device__ int   g_rowptr[MAXN + 1];
__device__ int   g_wp[MAXN + 1];
__device__ int2  g_edge[MAXE];                     // packed (col, val-bits)
__device__ int   g_bsum[1024];
// W split into bf16 hi/lo planes, row-major [K=256][N=128]
__device__ __nv_bfloat16 g_Wh[INF * OUTF];
__device__ __nv_bfloat16 g_Wl[INF * OUTF];

// -------- side stream + events for fork-join graph capture --------
__global__ void warm_kernel() {}

struct SideStream {
    cudaStream_t s2;
    cudaEvent_t  ev_fork, ev_join;
    SideStream() {
        cudaStreamCreateWithFlags(&s2, cudaStreamNonBlocking);
        cudaEventCreateWithFlags(&ev_fork, cudaEventDisableTiming);
        cudaEventCreateWithFlags(&ev_join, cudaEventDisableTiming);
        warm_kernel<<<1, 32>>>();
        warm_kernel<<<1, 32, 0, s2>>>();
        cudaEventRecord(ev_fork, 0);
        cudaStreamWaitEvent(s2, ev_fork, 0);
        cudaEventRecord(ev_join, s2);
        cudaStreamWaitEvent(0, ev_join, 0);
        cudaDeviceSynchronize();
    }
};
static SideStream g_ss;

__device__ __forceinline__ unsigned short f2bf_bits(float f) {
    __nv_bfloat16 b = __float2bfloat16(f);
    return *reinterpret_cast<unsigned short*>(&b);
}
__device__ __forceinline__ float bf2f(unsigned short bits) {
    __nv_bfloat16 b;
    *reinterpret_cast<unsigned short*>(&b) = bits;
    return __bfloat162float(b);
}

// ============ W prep: hi/lo split (GEMM branch) ============
__global__ void wprep_kernel(const float* __restrict__ W,
                             __nv_bfloat16* __restrict__ Wh,
                             __nv_bfloat16* __restrict__ Wl)
{
    int idx = blockIdx.x * 256 + threadIdx.x;
    if (idx < INF * OUTF) {
        float w = W[idx];
        unsigned short hb = f2bf_bits(w);
        unsigned short lb = f2bf_bits(w - bf2f(hb));
        *reinterpret_cast<unsigned short*>(&Wh[idx]) = hb;
        *reinterpret_cast<unsigned short*>(&Wl[idx]) = lb;
    }
}

// ============ zero cnt (CSR branch) ============
__global__ void zero_cnt_kernel(int* cnt, int n)
{
    int i = blockIdx.x * blockDim.x + threadIdx.x;
    if (i <= n) cnt[i] = 0;
}

// ============ GEMM via wmma (HMMA bf16), split-bf16, cp.async pipelined ======
#define BK 64
#define A_LD 72
#define A_ROW_B (A_LD * 2)
#define W_LD 136
#define W_ROW_B (W_LD * 2)
#define SM_AH 0
#define SM_AL (SM_AH + 128 * A_ROW_B)
#define SM_WH (SM_AL + 128 * A_ROW_B)
#define SM_WL (SM_WH + 64 * W_ROW_B)
#define SM_XS (SM_WL + 64 * W_ROW_B)
#define SM_TOTAL (SM_XS + 128 * 256)               // 104448

__device__ __forceinline__ void cp_async16(uint32_t saddr, const void* gptr) {
    asm volatile("cp.async.cg.shared.global [%0], [%1], 16;"
                 :: "r"(saddr), "l"(gptr));
}
__device__ __forceinline__ void cp_async_commit() {
    asm volatile("cp.async.commit_group;");
}
__device__ __forceinline__ void cp_async_wait0() {
    asm volatile("cp.async.wait_group 0;" ::: "memory");
}

__device__ __forceinline__ uint32_t smem_u32(const void* p) {
    uint32_t a;
    asm("{ .reg .u64 t; cvta.to.shared.u64 t, %1; cvt.u32.u64 %0, t; }"
        : "=r"(a) : "l"(p));
    return a;
}

__global__ __launch_bounds__(256, 2) void gemm_wmma_kernel(
    const float* __restrict__ X,
    const __nv_bfloat16* __restrict__ Wh,
    const __nv_bfloat16* __restrict__ Wl,
    __half* __restrict__ SH, int nrows)
{
    extern __shared__ char smem[];
    const int tid = threadIdx.x;
    const int wid = tid >> 5;
    const int bm = blockIdx.x * 128;
    const int warpM = wid >> 1;
    const int warpN = wid & 1;
    const uint32_t xs_base = smem_u32(smem + SM_XS);

    wmma::fragment<wmma::accumulator, 16, 16, 16, float> acc[2][4];
#pragma unroll
    for (int i = 0; i < 2; i++)
#pragma unroll
        for (int j = 0; j < 4; j++)
            wmma::fill_fragment(acc[i][j], 0.0f);

    {
#pragma unroll
        for (int it = 0; it < 8; it++) {
            int idx = tid + it * 256;
            int r = idx >> 4, c4 = idx & 15;
            int grow = bm + r;
            uint32_t so = xs_base + (uint32_t)r * 256 + (uint32_t)c4 * 16;
            if (grow < nrows)
                cp_async16(so, X + (size_t)grow * INF + c4 * 4);
            else
                *reinterpret_cast<uint4*>(smem + SM_XS + r * 256 + c4 * 16) =
                    make_uint4(0u, 0u, 0u, 0u);
        }
        cp_async_commit();
    }

    for (int c = 0; c < 4; c++) {
        cp_async_wait0();
        __syncthreads();
#pragma unroll
        for (int it = 0; it < 8; it++) {
            int idx = tid + it * 256;
            int r = idx >> 4, c4 = idx & 15;
            float4 f = *reinterpret_cast<const float4*>(smem + SM_XS + r * 256 + c4 * 16);
            unsigned short h0 = f2bf_bits(f.x), h1 = f2bf_bits(f.y);
            unsigned short h2 = f2bf_bits(f.z), h3 = f2bf_bits(f.w);
            unsigned short l0 = f2bf_bits(f.x - bf2f(h0));
            unsigned short l1 = f2bf_bits(f.y - bf2f(h1));
            unsigned short l2 = f2bf_bits(f.z - bf2f(h2));
            unsigned short l3 = f2bf_bits(f.w - bf2f(h3));
            uint2 hv = make_uint2((uint32_t)h0 | ((uint32_t)h1 << 16),
                                  (uint32_t)h2 | ((uint32_t)h3 << 16));
            uint2 lv = make_uint2((uint32_t)l0 | ((uint32_t)l1 << 16),
                                  (uint32_t)l2 | ((uint32_t)l3 << 16));
            uint32_t off = (uint32_t)r * A_ROW_B + (uint32_t)c4 * 8;
            *reinterpret_cast<uint2*>(smem + SM_AH + off) = hv;
            *reinterpret_cast<uint2*>(smem + SM_AL + off) = lv;
        }
#pragma unroll
        for (int it = 0; it < 4; it++) {
            int idx = tid + it * 256;
            int r = idx >> 4, cc = idx & 15;
            uint32_t doff = (uint32_t)r * W_ROW_B + (uint32_t)cc * 16;
            *reinterpret_cast<uint4*>(smem + SM_WH + doff) =
                *(reinterpret_cast<const uint4*>(Wh + (size_t)(c * BK + r) * OUTF) + cc);
            *reinterpret_cast<uint4*>(smem + SM_WL + doff) =
                *(reinterpret_cast<const uint4*>(Wl + (size_t)(c * BK + r) * OUTF) + cc);
        }
        __syncthreads();

        if (c < 3) {
#pragma unroll
            for (int it = 0; it < 8; it++) {
                int idx = tid + it * 256;
                int r = idx >> 4, c4 = idx & 15;
                int grow = bm + r;
                uint32_t so = xs_base + (uint32_t)r * 256 + (uint32_t)c4 * 16;
                if (grow < nrows)
                    cp_async16(so, X + (size_t)grow * INF + (c + 1) * BK + c4 * 4);
            }
            cp_async_commit();
        }

        const __nv_bfloat16* AH = reinterpret_cast<const __nv_bfloat16*>(smem + SM_AH);
        const __nv_bfloat16* AL = reinterpret_cast<const __nv_bfloat16*>(smem + SM_AL);
        const __nv_bfloat16* WHs = reinterpret_cast<const __nv_bfloat16*>(smem + SM_WH);
        const __nv_bfloat16* WLs = reinterpret_cast<const __nv_bfloat16*>(smem + SM_WL);

#pragma unroll
        for (int ks = 0; ks < 4; ks++) {
            wmma::fragment<wmma::matrix_a, 16, 16, 16, __nv_bfloat16, wmma::row_major> ah[2], al[2];
#pragma unroll
            for (int i = 0; i < 2; i++) {
                int arow = warpM * 32 + i * 16;
                wmma::load_matrix_sync(ah[i], AH + arow * A_LD + ks * 16, A_LD);
                wmma::load_matrix_sync(al[i], AL + arow * A_LD + ks * 16, A_LD);
            }
#pragma unroll
            for (int j = 0; j < 4; j++) {
                wmma::fragment<wmma::matrix_b, 16, 16, 16, __nv_bfloat16, wmma::row_major> bh, bl;
                int bcol = warpN * 64 + j * 16;
                wmma::load_matrix_sync(bh, WHs + (ks * 16) * W_LD + bcol, W_LD);
                wmma::load_matrix_sync(bl, WLs + (ks * 16) * W_LD + bcol, W_LD);
#pragma unroll
                for (int i = 0; i < 2; i++) {
                    wmma::mma_sync(acc[i][j], ah[i], bh, acc[i][j]);
                    wmma::mma_sync(acc[i][j], ah[i], bl, acc[i][j]);
                    wmma::mma_sync(acc[i][j], al[i], bh, acc[i][j]);
                }
            }
        }
        __syncthreads();
    }

    // ---- epilogue: stage fp32 via smem, convert to fp16, coalesced store ----
    float* F = reinterpret_cast<float*>(smem);
#pragma unroll
    for (int i = 0; i < 2; i++)
#pragma unroll
        for (int j = 0; j < 4; j++)
            wmma::store_matrix_sync(F + (warpM * 32 + i * 16) * 128 + warpN * 64 + j * 16,
                                    acc[i][j], 128, wmma::mem_row_major);
    __syncthreads();
    const float4* F4 = reinterpret_cast<const float4*>(F);
    uint2* SH2 = reinterpret_cast<uint2*>(SH);
#pragma unroll
    for (int it = 0; it < 16; it++) {
        int idx = tid + it * 256;
        int r = idx >> 5, c4 = idx & 31;
        int grow = bm + r;
        if (grow < nrows) {
            float4 f = F4[idx];
            __half2 p0 = __floats2half2_rn(f.x, f.y);
            __half2 p1 = __floats2half2_rn(f.z, f.w);
            SH2[(size_t)grow * 32 + c4] =
                make_uint2(*reinterpret_cast<uint32_t*>(&p0),
                           *reinterpret_cast<uint32_t*>(&p1));
        }
    }
}

// ================= CSR build =================
__global__ void hist_kernel(const int* __restrict__ row, int* __restrict__ cnt, int E)
{
    int b = blockIdx.x * blockDim.x + threadIdx.x;
    int e = b * 4;
    if (e + 3 < E) {
        int4 r4 = *reinterpret_cast<const int4*>(row + e);
        atomicAdd(&cnt[r4.x], 1);
        atomicAdd(&cnt[r4.y], 1);
        atomicAdd(&cnt[r4.z], 1);
        atomicAdd(&cnt[r4.w], 1);
    } else {
        for (int k = e; k < E; k++) atomicAdd(&cnt[row[k]], 1);
    }
}

__global__ __launch_bounds__(1024) void scan1_kernel(
    const int* __restrict__ cnt, int* __restrict__ excl, int* __restrict__ bsum, int n)
{
    __shared__ int s[1024];
    int t = threadIdx.x;
    int gid = blockIdx.x * 1024 + t;
    int v = (gid < n) ? cnt[gid] : 0;
    s[t] = v;
    __syncthreads();
#pragma unroll
    for (int off = 1; off < 1024; off <<= 1) {
        int x = (t >= off) ? s[t - off] : 0;
        __syncthreads();
        s[t] += x;
        __syncthreads();
    }
    if (gid < n) excl[gid] = s[t] - v;
    if (t == 1023) bsum[blockIdx.x] = s[1023];
}

__global__ __launch_bounds__(1024) void scan2_kernel(int* bsum, int nb)
{
    __shared__ int s[1024];
    int t = threadIdx.x;
    int v = (t < nb) ? bsum[t] : 0;
    s[t] = v;
    __syncthreads();
#pragma unroll
    for (int off = 1; off < 1024; off <<= 1) {
        int x = (t >= off) ? s[t - off] : 0;
        __syncthreads();
        s[t] += x;
        __syncthreads();
    }
    if (t < nb) bsum[t] = s[t] - v;
}

__global__ void scan3_kernel(int* __restrict__ rowptr, int* __restrict__ wp,
                             const int* __restrict__ bsum, int n, int E)
{
    int i = blockIdx.x * blockDim.x + threadIdx.x;
    if (i < n) {
        int v = rowptr[i] + bsum[i >> 10];
        rowptr[i] = v;
        wp[i] = v;
    }
    if (i == 0) rowptr[n] = E;
}

__global__ void scatter_kernel(const int* __restrict__ row, const int* __restrict__ col,
                               const float* __restrict__ vals, int* __restrict__ wp,
                               int2* __restrict__ edge, int E)
{
    int b = blockIdx.x * blockDim.x + threadIdx.x;
    int e = b * 4;
    if (e + 3 < E) {
        int4   r4 = *reinterpret_cast<const int4*>(row + e);
        int4   c4 = *reinterpret_cast<const int4*>(col + e);
        float4 v4 = *reinterpret_cast<const float4*>(vals + e);
        int p;
        p = atomicAdd(&wp[r4.x], 1); edge[p] = make_int2(c4.x, __float_as_int(v4.x));
        p = atomicAdd(&wp[r4.y], 1); edge[p] = make_int2(c4.y, __float_as_int(v4.y));
        p = atomicAdd(&wp[r4.z], 1); edge[p] = make_int2(c4.z, __float_as_int(v4.z));
        p = atomicAdd(&wp[r4.w], 1); edge[p] = make_int2(c4.w, __float_as_int(v4.w));
    } else {
        for (int k = e; k < E; k++) {
            int p = atomicAdd(&wp[row[k]], 1);
            edge[p] = make_int2(col[k], __float_as_int(vals[k]));
        }
    }
}

// ======= SpMM (fp16 gather, MLP=8): out[r] = sum val*support16[col] + bias ===
__global__ __launch_bounds__(256) void spmm_kernel(
    const int* __restrict__ rowptr, const int2* __restrict__ edge,
    const __half* __restrict__ SH,
    const float* __restrict__ bias, float* __restrict__ out, int nrows)
{
    int warp = (blockIdx.x * blockDim.x + threadIdx.x) >> 5;
    int lane = threadIdx.x & 31;
    if (warp >= nrows) return;

    int start = rowptr[warp];
    int end   = rowptr[warp + 1];

    const uint2* S2 = reinterpret_cast<const uint2*>(SH);
    float4 acc = make_float4(0.f, 0.f, 0.f, 0.f);

    for (int j0 = start; j0 < end; j0 += 32) {
        int jj = j0 + lane;
        int2 ev = (jj < end) ? edge[jj] : make_int2(0, 0);
        int m = min(32, end - j0);
        int t = 0;
        for (; t + 8 <= m; t += 8) {
            int   c[8];
            float v[8];
            uint2 u[8];
#pragma unroll
            for (int q = 0; q < 8; q++) {
                c[q] = __shfl_sync(0xffffffffu, ev.x, t + q);
                v[q] = __int_as_float(__shfl_sync(0xffffffffu, ev.y, t + q));
            }
#pragma unroll
            for (int q = 0; q < 8; q++)
                u[q] = S2[(size_t)c[q] * 32 + lane];
#pragma unroll
            for (int q = 0; q < 8; q++) {
                __half2 h01 = *reinterpret_cast<__half2*>(&u[q].x);
                __half2 h23 = *reinterpret_cast<__half2*>(&u[q].y);
                float2 f01 = __half22float2(h01);
                float2 f23 = __half22float2(h23);
                acc.x = fmaf(v[q], f01.x, acc.x);
                acc.y = fmaf(v[q], f01.y, acc.y);
                acc.z = fmaf(v[q], f23.x, acc.z);
                acc.w = fmaf(v[q], f23.y, acc.w);
            }
        }
        for (; t < m; t++) {
            int   ct = __shfl_sync(0xffffffffu, ev.x, t);
            float vt = __int_as_float(__shfl_sync(0xffffffffu, ev.y, t));
            uint2 u = S2[(size_t)ct * 32 + lane];
            __half2 h01 = *reinterpret_cast<__half2*>(&u.x);
            __half2 h23 = *reinterpret_cast<__half2*>(&u.y);
            float2 f01 = __half22float2(h01);
            float2 f23 = __half22float2(h23);
            acc.x = fmaf(vt, f01.x, acc.x);
            acc.y = fmaf(vt, f01.y, acc.y);
            acc.z = fmaf(vt, f23.x, acc.z);
            acc.w = fmaf(vt, f23.y, acc.w);
        }
    }

    float4 b = reinterpret_cast<const float4*>(bias)[lane];
    acc.x += b.x; acc.y += b.y; acc.z += b.z; acc.w += b.w;
    reinterpret_cast<float4*>(out)[(size_t)warp * 32 + lane] = acc;
}

// ================= launch =================
extern "C" void kernel_launch(void* const* d_in, const int* in_sizes, int n_in,
                              void* d_out, int out_size)
{
    const float* x        = (const float*)d_in[0];   // [N, IN]
    const float* adj_vals = (const float*)d_in[1];   // [E]
    const float* weight   = (const float*)d_in[2];   // [IN, OUT]
    const float* bias     = (const float*)d_in[3];   // [OUT]
    const int*   row      = (const int*)d_in[4];     // [E]
    const int*   col      = (const int*)d_in[5];     // [E]

    const int outf = in_sizes[3];                    // 128
    const int inf  = in_sizes[2] / outf;             // 256
    const int N    = in_sizes[0] / inf;              // 100000
    const int E    = in_sizes[1];                    // 3200000
    (void)inf; (void)n_in; (void)out_size;

    __half* supportH; cudaGetSymbolAddress((void**)&supportH, g_supportH);
    int*    cnt;      cudaGetSymbolAddress((void**)&cnt,     g_cnt);
    int*    rowptr;   cudaGetSymbolAddress((void**)&rowptr,  g_rowptr);
    int*    wp;       cudaGetSymbolAddress((void**)&wp,      g_wp);
    int2*   edge;     cudaGetSymbolAddress((void**)&edge,    g_edge);
    int*    bsum;     cudaGetSymbolAddress((void**)&bsum,    g_bsum);
    __nv_bfloat16* wh; cudaGetSymbolAddress((void**)&wh, g_Wh);
    __nv_bfloat16* wl; cudaGetSymbolAddress((void**)&wl, g_Wl);

    cudaStream_t s2 = g_ss.s2;

    // ---- fork: CSR branch on s2, GEMM branch on legacy stream ----
    cudaEventRecord(g_ss.ev_fork, 0);
    cudaStreamWaitEvent(s2, g_ss.ev_fork, 0);

    // Branch A: W split + tensor-core split-bf16 GEMM (fp16 output)
    wprep_kernel<<<(INF * OUTF + 255) / 256, 256>>>(weight, wh, wl);
    cudaFuncSetAttribute(gemm_wmma_kernel,
                         cudaFuncAttributeMaxDynamicSharedMemorySize, SM_TOTAL);
    gemm_wmma_kernel<<<(N + 127) / 128, 256, SM_TOTAL>>>(x, wh, wl, supportH, N);

    // Branch B: CSR build (packed edges)
    zero_cnt_kernel<<<(N + 256) / 256, 256, 0, s2>>>(cnt, N);
    hist_kernel<<<(E / 4 + 255) / 256, 256, 0, s2>>>(row, cnt, E);
    int nb = (N + 1023) / 1024;
    scan1_kernel<<<nb, 1024, 0, s2>>>(cnt, rowptr, bsum, N);
    scan2_kernel<<<1, 1024, 0, s2>>>(bsum, nb);
    scan3_kernel<<<(N + 255) / 256, 256, 0, s2>>>(rowptr, wp, bsum, N, E);
    scatter_kernel<<<(E / 4 + 255) / 256, 256, 0, s2>>>(row, col, adj_vals, wp, edge, E);

    // ---- join: SpMM needs both branches ----
    cudaEventRecord(g_ss.ev_join, s2);
    cudaStreamWaitEvent(0, g_ss.ev_join, 0);

    spmm_kernel<<<(N + 7) / 8, 256>>>(rowptr, edge, supportH, bias,
                                      (float*)d_out, N);
}